// round 5
// baseline (speedup 1.0000x reference)
#include <cuda_runtime.h>
#include <cuda_bf16.h>
#include <math.h>
#include <stdint.h>

typedef uint32_t u32;

#define BB 16
#define TT 1024
#define HH 512
#define G4 2048
#define KK 512
#define NB 128

// ---------------- device-global scratch ------------------------------------------
__device__ __align__(16) float g_gx[BB * TT * G4];   // 128 MB
__device__ __align__(16) float g_y [BB * TT * HH];   // 32 MB
__device__ __align__(16) float g_h [2][BB * HH];
__device__ __align__(16) __nv_bfloat16 g_ahi[BB * TT * HH];
__device__ __align__(16) __nv_bfloat16 g_alo[BB * TT * HH];
__device__ __align__(16) __nv_bfloat16 g_whi[2][G4 * KK];
__device__ __align__(16) __nv_bfloat16 g_wlo[2][G4 * KK];
__device__ unsigned int g_bar_count;
__device__ unsigned int g_bar_gen;

// ---------------- PTX helpers -----------------------------------------------------
__device__ __forceinline__ u32 cvta_s(const void* p) {
    return (u32)__cvta_generic_to_shared(p);
}
__device__ __forceinline__ void cpa16(u32 dst, const void* src) {
    asm volatile("cp.async.cg.shared.global [%0], [%1], 16;" :: "r"(dst), "l"(src));
}
__device__ __forceinline__ void ldsm4(u32* r, u32 addr) {
    asm volatile("ldmatrix.sync.aligned.m8n8.x4.shared.b16 {%0,%1,%2,%3}, [%4];"
        : "=r"(r[0]), "=r"(r[1]), "=r"(r[2]), "=r"(r[3]) : "r"(addr));
}
__device__ __forceinline__ void ldsm2(u32* r, u32 addr) {
    asm volatile("ldmatrix.sync.aligned.m8n8.x2.shared.b16 {%0,%1}, [%2];"
        : "=r"(r[0]), "=r"(r[1]) : "r"(addr));
}
__device__ __forceinline__ void mma16816(float* d, const u32* a, const u32* b) {
    asm volatile(
        "mma.sync.aligned.m16n8k16.row.col.f32.bf16.bf16.f32 "
        "{%0,%1,%2,%3}, {%4,%5,%6,%7}, {%8,%9}, {%0,%1,%2,%3};"
        : "+f"(d[0]), "+f"(d[1]), "+f"(d[2]), "+f"(d[3])
        : "r"(a[0]), "r"(a[1]), "r"(a[2]), "r"(a[3]), "r"(b[0]), "r"(b[1]));
}

// ---------------- grid-wide barrier -----------------------------------------------
__device__ __forceinline__ void grid_barrier(unsigned nb)
{
    __syncthreads();
    if (threadIdx.x == 0) {
        __threadfence();
        volatile unsigned* vgen = (volatile unsigned*)&g_bar_gen;
        unsigned gen = *vgen;
        unsigned t = atomicAdd(&g_bar_count, 1u);
        if (t == nb - 1u) {
            atomicExch(&g_bar_count, 0u);
            __threadfence();
            atomicAdd(&g_bar_gen, 1u);
        } else {
            while (*vgen == gen) { }
        }
        __threadfence();
    }
    __syncthreads();
}

// ---------------- fp32 -> (bf16 hi, bf16 lo) split --------------------------------
__global__ void conv_split(const float* __restrict__ src, int useY,
                           __nv_bfloat16* __restrict__ hi,
                           __nv_bfloat16* __restrict__ lo, int n4)
{
    const float* s = useY ? g_y : src;
    int i = blockIdx.x * blockDim.x + threadIdx.x;
    if (i >= n4) return;
    float4 v = ((const float4*)s)[i];
    __nv_bfloat16 ha = __float2bfloat16(v.x);
    __nv_bfloat16 hb = __float2bfloat16(v.y);
    __nv_bfloat16 hc = __float2bfloat16(v.z);
    __nv_bfloat16 hd = __float2bfloat16(v.w);
    __nv_bfloat16 la = __float2bfloat16(v.x - __bfloat162float(ha));
    __nv_bfloat16 lb = __float2bfloat16(v.y - __bfloat162float(hb));
    __nv_bfloat16 lc = __float2bfloat16(v.z - __bfloat162float(hc));
    __nv_bfloat16 ld = __float2bfloat16(v.w - __bfloat162float(hd));
    __nv_bfloat162 ph0; ph0.x = ha; ph0.y = hb;
    __nv_bfloat162 ph1; ph1.x = hc; ph1.y = hd;
    __nv_bfloat162 pl0; pl0.x = la; pl0.y = lb;
    __nv_bfloat162 pl1; pl1.x = lc; pl1.y = ld;
    ((__nv_bfloat162*)hi)[2 * i]     = ph0;
    ((__nv_bfloat162*)hi)[2 * i + 1] = ph1;
    ((__nv_bfloat162*)lo)[2 * i]     = pl0;
    ((__nv_bfloat162*)lo)[2 * i + 1] = pl1;
}

// ---------------- bf16-split HMMA GEMM (unchanged from round 4) -------------------
#define LDR_B   80
#define TILE_B  (128 * LDR_B)
#define STAGE_B (4 * TILE_B)
#define GSTG    16
#define SMEM_DYN (2 * STAGE_B)

__global__ __launch_bounds__(256, 1)
void gemm_hmma(const __nv_bfloat16* __restrict__ ahi,
               const __nv_bfloat16* __restrict__ alo,
               const __nv_bfloat16* __restrict__ whi,
               const __nv_bfloat16* __restrict__ wlo,
               const float* __restrict__ b1, const float* __restrict__ b2)
{
    extern __shared__ char dsm[];
    __shared__ float sbias[128];

    const int tid = threadIdx.x;
    const int wid = tid >> 5;
    const int lid = tid & 31;
    const int wm = wid >> 2;
    const int wn = wid & 3;
    const int bm = blockIdx.y * 128;
    const int bn = blockIdx.x * 128;

    const u32 sbase = cvta_s(dsm);
    if (tid < 128) sbias[tid] = b1[bn + tid] + b2[bn + tid];

    auto copy_stage = [&](int kt, int bsel) {
        const __nv_bfloat16* srcs[4] = {
            ahi + (size_t)bm * KK + kt * 32,
            alo + (size_t)bm * KK + kt * 32,
            whi + (size_t)bn * KK + kt * 32,
            wlo + (size_t)bn * KK + kt * 32 };
        u32 st = sbase + bsel * STAGE_B;
#pragma unroll
        for (int t = 0; t < 4; t++) {
            u32 tb = st + t * TILE_B;
            const __nv_bfloat16* sp = srcs[t];
#pragma unroll
            for (int i = 0; i < 2; i++) {
                int c = tid + 256 * i;
                int row = c >> 2, kc = c & 3;
                cpa16(tb + row * LDR_B + kc * 16, sp + (size_t)row * KK + kc * 8);
            }
        }
        asm volatile("cp.async.commit_group;" ::: "memory");
    };

    float d[4][4][4];
#pragma unroll
    for (int mt = 0; mt < 4; mt++)
#pragma unroll
        for (int nt = 0; nt < 4; nt++)
#pragma unroll
            for (int q = 0; q < 4; q++) d[mt][nt][q] = 0.f;

    copy_stage(0, 0);
    copy_stage(1, 1);

    const u32 aoff = (u32)((wm * 64 + (lid & 15)) * LDR_B + (lid >> 4) * 16);
    const u32 boff = (u32)((wn * 32 + (lid & 7)) * LDR_B + ((lid >> 3) & 1) * 16);

    for (int s = 0; s < GSTG; s++) {
        if (s == GSTG - 1) asm volatile("cp.async.wait_group 0;" ::: "memory");
        else               asm volatile("cp.async.wait_group 1;" ::: "memory");
        __syncthreads();

        u32 st = sbase + (s & 1) * STAGE_B;
#pragma unroll
        for (int ks = 0; ks < 2; ks++) {
            u32 ah[4][4], al[4][4], bh[4][2], bl[4][2];
#pragma unroll
            for (int mt = 0; mt < 4; mt++) {
                u32 a = st + aoff + mt * (16 * LDR_B) + ks * 32;
                ldsm4(ah[mt], a);
                ldsm4(al[mt], a + TILE_B);
            }
#pragma unroll
            for (int nt = 0; nt < 4; nt++) {
                u32 b = st + 2 * TILE_B + boff + nt * (8 * LDR_B) + ks * 32;
                ldsm2(bh[nt], b);
                ldsm2(bl[nt], b + TILE_B);
            }
#pragma unroll
            for (int mt = 0; mt < 4; mt++)
#pragma unroll
                for (int nt = 0; nt < 4; nt++) {
                    mma16816(d[mt][nt], ah[mt], bh[nt]);
                    mma16816(d[mt][nt], ah[mt], bl[nt]);
                    mma16816(d[mt][nt], al[mt], bh[nt]);
                }
        }
        __syncthreads();
        if (s + 2 < GSTG) copy_stage(s + 2, s & 1);
    }

    const int r0 = lid >> 2;
    const int c0 = 2 * (lid & 3);
#pragma unroll
    for (int mt = 0; mt < 4; mt++) {
#pragma unroll
        for (int nt = 0; nt < 4; nt++) {
            int m = bm + wm * 64 + mt * 16 + r0;
            int col = wn * 32 + nt * 8 + c0;
            float* cp0 = &g_gx[(size_t)m * G4 + bn + col];
            float* cp1 = &g_gx[(size_t)(m + 8) * G4 + bn + col];
            float2 v0 = { d[mt][nt][0] + sbias[col],
                          d[mt][nt][1] + sbias[col + 1] };
            float2 v1 = { d[mt][nt][2] + sbias[col],
                          d[mt][nt][3] + sbias[col + 1] };
            *(float2*)cp0 = v0;
            *(float2*)cp1 = v1;
        }
    }
}

// ---------------- persistent LSTM scan — latency-collapsed ------------------------
// 128 CTAs x 256 threads. FMA mapping: kq = lane>>1 (16-way k-split IN-LANE),
// (bq,rq) = (warp<<1)|(lane&1). In-warp 4-level shuffle reduction (no smem
// partial phase). One sum exchange via smem, then 256-thread act phase (one gate
// per thread, MUFU parallel), quad-shuffle gather, c in registers.
__global__ __launch_bounds__(256, 1)
void lstm_scan_kernel(const float* __restrict__ w_hh,
                      const float* __restrict__ h0,
                      const float* __restrict__ c0,
                      float* __restrict__ hout,
                      int write_y)
{
    __shared__ float sh_h[16 * 545];   // lanes hit all 32 banks: 545 odd, kq*34 even
    __shared__ float ssum[16 * 17];    // stride 17: conflict-free STS/LDS

    const int tid  = threadIdx.x;
    const int bid  = blockIdx.x;
    const int lane = tid & 31;
    const int wrp  = tid >> 5;
    const int kq   = lane >> 1;                 // 0..15, in-lane
    const int pr   = (wrp << 1) | (lane & 1);   // 0..15
    const int bq   = pr & 3;
    const int rq   = pr >> 2;

    // register-resident w_hh slice (rows rq*512 + bid*4 + jj, k = kq*32..+31)
    float wreg[4][32];
#pragma unroll
    for (int jj = 0; jj < 4; jj++) {
        const float* wr = &w_hh[(size_t)(rq * HH + bid * 4 + jj) * HH + kq * 32];
#pragma unroll
        for (int kk = 0; kk < 32; kk++) wreg[jj][kk] = wr[kk];
    }

    // act-phase identity: batch ab, column aj, gate ag
    const int ab = tid >> 4;
    const int aj = (tid >> 2) & 3;
    const int ag = tid & 3;
    const int lb = lane & 28;                  // quad base lane
    const size_t gx_base = (size_t)ab * TT * G4 + ag * HH + bid * 4 + aj;

    float c_reg = 0.f;
    if (ag == 0) c_reg = c0[ab * HH + bid * 4 + aj];
    if (tid < 64) g_h[0][bid * 64 + tid] = h0[bid * 64 + tid];
    grid_barrier(NB);

    float gxv = __ldg(&g_gx[gx_base]);

#pragma unroll 1
    for (int t = 0; t < TT; t++) {
        // stage h (L2 broadcast; __ldcg avoids stale L1 across steps)
        const float* cur = g_h[t & 1];
#pragma unroll
        for (int p = 0; p < 32; p++) {
            int i = tid + 256 * p;
            int b = i >> 9, k = i & 511;
            sh_h[b * 545 + (k >> 5) * 34 + (k & 31)] = __ldcg(&cur[i]);
        }
        __syncthreads();

        // prefetch next step's gx under the FMA block
        float gxn = (t + 1 < TT) ? __ldg(&g_gx[gx_base + (size_t)(t + 1) * G4]) : 0.f;

        float acc[4][4];
#pragma unroll
        for (int jj = 0; jj < 4; jj++)
#pragma unroll
            for (int b2 = 0; b2 < 4; b2++) acc[jj][b2] = 0.f;

        const float* hb = &sh_h[kq * 34];
#pragma unroll
        for (int kk = 0; kk < 32; kk++) {
            float hv0 = hb[(4 * bq + 0) * 545 + kk];
            float hv1 = hb[(4 * bq + 1) * 545 + kk];
            float hv2 = hb[(4 * bq + 2) * 545 + kk];
            float hv3 = hb[(4 * bq + 3) * 545 + kk];
#pragma unroll
            for (int jj = 0; jj < 4; jj++) {
                float w = wreg[jj][kk];
                acc[jj][0] += w * hv0;
                acc[jj][1] += w * hv1;
                acc[jj][2] += w * hv2;
                acc[jj][3] += w * hv3;
            }
        }

        // full k-reduction in-warp: kq lives in lane bits 1..4
#pragma unroll
        for (int m = 2; m <= 16; m <<= 1)
#pragma unroll
            for (int jj = 0; jj < 4; jj++)
#pragma unroll
                for (int b2 = 0; b2 < 4; b2++)
                    acc[jj][b2] += __shfl_xor_sync(0xffffffffu, acc[jj][b2], m);

        if (kq == 0) {   // lanes 0,1 of each warp hold final sums
#pragma unroll
            for (int jj = 0; jj < 4; jj++)
#pragma unroll
                for (int b2 = 0; b2 < 4; b2++)
                    ssum[(4 * bq + b2) * 17 + rq * 4 + jj] = acc[jj][b2];
        }
        __syncthreads();

        // activation: one gate value per thread, MUFU fully parallel
        float s = ssum[ab * 17 + ag * 4 + aj] + gxv;
        float v = (ag == 2) ? tanhf(s) : 1.0f / (1.0f + expf(-s));

        float vi = __shfl_sync(0xffffffffu, v, lb | 0);
        float vf = __shfl_sync(0xffffffffu, v, lb | 1);
        float vg = __shfl_sync(0xffffffffu, v, lb | 2);
        float vo = __shfl_sync(0xffffffffu, v, lb | 3);

        if (ag == 0) {
            float c = vf * c_reg + vi * vg;
            c_reg = c;
            float h = vo * tanhf(c);
            int col = bid * 4 + aj;
            g_h[(t + 1) & 1][ab * HH + col] = h;
            if (write_y) g_y[((size_t)ab * TT + t) * HH + col] = h;
            if (t == TT - 1) hout[ab * HH + col] = h;
        }
        gxv = gxn;
        grid_barrier(NB);
    }
}

// ---------------- launch -----------------------------------------------------------
extern "C" void kernel_launch(void* const* d_in, const int* in_sizes, int n_in,
                              void* d_out, int out_size)
{
    const float* x     = (const float*)d_in[0];
    const float* h0    = (const float*)d_in[1];
    const float* c0    = (const float*)d_in[2];
    const float* w_ih0 = (const float*)d_in[3];
    const float* w_hh0 = (const float*)d_in[4];
    const float* b_ih0 = (const float*)d_in[5];
    const float* b_hh0 = (const float*)d_in[6];
    const float* w_ih1 = (const float*)d_in[7];
    const float* w_hh1 = (const float*)d_in[8];
    const float* b_ih1 = (const float*)d_in[9];
    const float* b_hh1 = (const float*)d_in[10];
    float* out = (float*)d_out;

    cudaFuncSetAttribute(gemm_hmma, cudaFuncAttributeMaxDynamicSharedMemorySize,
                         SMEM_DYN);

    __nv_bfloat16 *ahi, *alo, *w0hi, *w0lo, *w1hi, *w1lo;
    cudaGetSymbolAddress((void**)&ahi,  g_ahi);
    cudaGetSymbolAddress((void**)&alo,  g_alo);
    cudaGetSymbolAddress((void**)&w0hi, g_whi); w1hi = w0hi + G4 * KK;
    cudaGetSymbolAddress((void**)&w0lo, g_wlo); w1lo = w0lo + G4 * KK;

    const int NW4 = (G4 * KK) / 4;
    const int NA4 = (BB * TT * HH) / 4;
    dim3 ggrid(G4 / 128, (BB * TT) / 128);

    conv_split<<<(NW4 + 255) / 256, 256>>>(w_ih0, 0, w0hi, w0lo, NW4);
    conv_split<<<(NW4 + 255) / 256, 256>>>(w_ih1, 0, w1hi, w1lo, NW4);

    // layer 0
    conv_split<<<(NA4 + 255) / 256, 256>>>(x, 0, ahi, alo, NA4);
    gemm_hmma<<<ggrid, 256, SMEM_DYN>>>(ahi, alo, w0hi, w0lo, b_ih0, b_hh0);
    lstm_scan_kernel<<<NB, 256>>>(w_hh0, h0, c0, out, 1);

    // layer 1
    conv_split<<<(NA4 + 255) / 256, 256>>>(nullptr, 1, ahi, alo, NA4);
    gemm_hmma<<<ggrid, 256, SMEM_DYN>>>(ahi, alo, w1hi, w1lo, b_ih1, b_hh1);
    lstm_scan_kernel<<<NB, 256>>>(w_hh1, h0 + BB * HH, c0 + BB * HH, out + BB * HH, 0);
}

// round 9
// speedup vs baseline: 1.2045x; 1.2045x over previous
#include <cuda_runtime.h>
#include <cuda_bf16.h>
#include <math.h>
#include <stdint.h>

typedef uint32_t u32;

#define BB 16
#define TT 1024
#define HH 512
#define G4 2048
#define KK 512
#define NB 128

// ---------------- device-global scratch ------------------------------------------
__device__ __align__(16) float g_gx[BB * TT * G4];   // 128 MB
__device__ __align__(16) float g_y [BB * TT * HH];   // 32 MB
__device__ __align__(16) float g_h [2][BB * HH];
__device__ __align__(16) __nv_bfloat16 g_ahi[BB * TT * HH];
__device__ __align__(16) __nv_bfloat16 g_alo[BB * TT * HH];
__device__ __align__(16) __nv_bfloat16 g_whi[2][G4 * KK];
__device__ __align__(16) __nv_bfloat16 g_wlo[2][G4 * KK];
__device__ unsigned int g_bar_count;
__device__ unsigned int g_bar_gen;

// ---------------- PTX helpers -----------------------------------------------------
__device__ __forceinline__ u32 cvta_s(const void* p) {
    return (u32)__cvta_generic_to_shared(p);
}
__device__ __forceinline__ void cpa16(u32 dst, const void* src) {
    asm volatile("cp.async.cg.shared.global [%0], [%1], 16;" :: "r"(dst), "l"(src));
}
__device__ __forceinline__ void ldsm4(u32* r, u32 addr) {
    asm volatile("ldmatrix.sync.aligned.m8n8.x4.shared.b16 {%0,%1,%2,%3}, [%4];"
        : "=r"(r[0]), "=r"(r[1]), "=r"(r[2]), "=r"(r[3]) : "r"(addr));
}
__device__ __forceinline__ void ldsm2(u32* r, u32 addr) {
    asm volatile("ldmatrix.sync.aligned.m8n8.x2.shared.b16 {%0,%1}, [%2];"
        : "=r"(r[0]), "=r"(r[1]) : "r"(addr));
}
__device__ __forceinline__ void mma16816(float* d, const u32* a, const u32* b) {
    asm volatile(
        "mma.sync.aligned.m16n8k16.row.col.f32.bf16.bf16.f32 "
        "{%0,%1,%2,%3}, {%4,%5,%6,%7}, {%8,%9}, {%0,%1,%2,%3};"
        : "+f"(d[0]), "+f"(d[1]), "+f"(d[2]), "+f"(d[3])
        : "r"(a[0]), "r"(a[1]), "r"(a[2]), "r"(a[3]), "r"(b[0]), "r"(b[1]));
}

// ---------------- grid-wide barrier -----------------------------------------------
__device__ __forceinline__ void grid_barrier(unsigned nb)
{
    __syncthreads();
    if (threadIdx.x == 0) {
        __threadfence();
        volatile unsigned* vgen = (volatile unsigned*)&g_bar_gen;
        unsigned gen = *vgen;
        unsigned t = atomicAdd(&g_bar_count, 1u);
        if (t == nb - 1u) {
            atomicExch(&g_bar_count, 0u);
            __threadfence();
            atomicAdd(&g_bar_gen, 1u);
        } else {
            while (*vgen == gen) { }
        }
        __threadfence();
    }
    __syncthreads();
}

// ---------------- fp32 -> (bf16 hi, bf16 lo) split --------------------------------
__global__ void conv_split(const float* __restrict__ src, int useY,
                           __nv_bfloat16* __restrict__ hi,
                           __nv_bfloat16* __restrict__ lo, int n4)
{
    const float* s = useY ? g_y : src;
    int i = blockIdx.x * blockDim.x + threadIdx.x;
    if (i >= n4) return;
    float4 v = ((const float4*)s)[i];
    __nv_bfloat16 ha = __float2bfloat16(v.x);
    __nv_bfloat16 hb = __float2bfloat16(v.y);
    __nv_bfloat16 hc = __float2bfloat16(v.z);
    __nv_bfloat16 hd = __float2bfloat16(v.w);
    __nv_bfloat16 la = __float2bfloat16(v.x - __bfloat162float(ha));
    __nv_bfloat16 lb = __float2bfloat16(v.y - __bfloat162float(hb));
    __nv_bfloat16 lc = __float2bfloat16(v.z - __bfloat162float(hc));
    __nv_bfloat16 ld = __float2bfloat16(v.w - __bfloat162float(hd));
    __nv_bfloat162 ph0; ph0.x = ha; ph0.y = hb;
    __nv_bfloat162 ph1; ph1.x = hc; ph1.y = hd;
    __nv_bfloat162 pl0; pl0.x = la; pl0.y = lb;
    __nv_bfloat162 pl1; pl1.x = lc; pl1.y = ld;
    ((__nv_bfloat162*)hi)[2 * i]     = ph0;
    ((__nv_bfloat162*)hi)[2 * i + 1] = ph1;
    ((__nv_bfloat162*)lo)[2 * i]     = pl0;
    ((__nv_bfloat162*)lo)[2 * i + 1] = pl1;
}

// ---------------- bf16-split HMMA GEMM (round-4, proven) --------------------------
#define LDR_B   80
#define TILE_B  (128 * LDR_B)
#define STAGE_B (4 * TILE_B)
#define GSTG    16
#define SMEM_DYN (2 * STAGE_B)

__global__ __launch_bounds__(256, 1)
void gemm_hmma(const __nv_bfloat16* __restrict__ ahi,
               const __nv_bfloat16* __restrict__ alo,
               const __nv_bfloat16* __restrict__ whi,
               const __nv_bfloat16* __restrict__ wlo,
               const float* __restrict__ b1, const float* __restrict__ b2)
{
    extern __shared__ char dsm[];
    __shared__ float sbias[128];

    const int tid = threadIdx.x;
    const int wid = tid >> 5;
    const int lid = tid & 31;
    const int wm = wid >> 2;
    const int wn = wid & 3;
    const int bm = blockIdx.y * 128;
    const int bn = blockIdx.x * 128;

    const u32 sbase = cvta_s(dsm);
    if (tid < 128) sbias[tid] = b1[bn + tid] + b2[bn + tid];

    auto copy_stage = [&](int kt, int bsel) {
        const __nv_bfloat16* srcs[4] = {
            ahi + (size_t)bm * KK + kt * 32,
            alo + (size_t)bm * KK + kt * 32,
            whi + (size_t)bn * KK + kt * 32,
            wlo + (size_t)bn * KK + kt * 32 };
        u32 st = sbase + bsel * STAGE_B;
#pragma unroll
        for (int t = 0; t < 4; t++) {
            u32 tb = st + t * TILE_B;
            const __nv_bfloat16* sp = srcs[t];
#pragma unroll
            for (int i = 0; i < 2; i++) {
                int c = tid + 256 * i;
                int row = c >> 2, kc = c & 3;
                cpa16(tb + row * LDR_B + kc * 16, sp + (size_t)row * KK + kc * 8);
            }
        }
        asm volatile("cp.async.commit_group;" ::: "memory");
    };

    float d[4][4][4];
#pragma unroll
    for (int mt = 0; mt < 4; mt++)
#pragma unroll
        for (int nt = 0; nt < 4; nt++)
#pragma unroll
            for (int q = 0; q < 4; q++) d[mt][nt][q] = 0.f;

    copy_stage(0, 0);
    copy_stage(1, 1);

    const u32 aoff = (u32)((wm * 64 + (lid & 15)) * LDR_B + (lid >> 4) * 16);
    const u32 boff = (u32)((wn * 32 + (lid & 7)) * LDR_B + ((lid >> 3) & 1) * 16);

    for (int s = 0; s < GSTG; s++) {
        if (s == GSTG - 1) asm volatile("cp.async.wait_group 0;" ::: "memory");
        else               asm volatile("cp.async.wait_group 1;" ::: "memory");
        __syncthreads();

        u32 st = sbase + (s & 1) * STAGE_B;
#pragma unroll
        for (int ks = 0; ks < 2; ks++) {
            u32 ah[4][4], al[4][4], bh[4][2], bl[4][2];
#pragma unroll
            for (int mt = 0; mt < 4; mt++) {
                u32 a = st + aoff + mt * (16 * LDR_B) + ks * 32;
                ldsm4(ah[mt], a);
                ldsm4(al[mt], a + TILE_B);
            }
#pragma unroll
            for (int nt = 0; nt < 4; nt++) {
                u32 b = st + 2 * TILE_B + boff + nt * (8 * LDR_B) + ks * 32;
                ldsm2(bh[nt], b);
                ldsm2(bl[nt], b + TILE_B);
            }
#pragma unroll
            for (int mt = 0; mt < 4; mt++)
#pragma unroll
                for (int nt = 0; nt < 4; nt++) {
                    mma16816(d[mt][nt], ah[mt], bh[nt]);
                    mma16816(d[mt][nt], ah[mt], bl[nt]);
                    mma16816(d[mt][nt], al[mt], bh[nt]);
                }
        }
        __syncthreads();
        if (s + 2 < GSTG) copy_stage(s + 2, s & 1);
    }

    const int r0 = lid >> 2;
    const int c0 = 2 * (lid & 3);
#pragma unroll
    for (int mt = 0; mt < 4; mt++) {
#pragma unroll
        for (int nt = 0; nt < 4; nt++) {
            int m = bm + wm * 64 + mt * 16 + r0;
            int col = wn * 32 + nt * 8 + c0;
            float* cp0 = &g_gx[(size_t)m * G4 + bn + col];
            float* cp1 = &g_gx[(size_t)(m + 8) * G4 + bn + col];
            float2 v0 = { d[mt][nt][0] + sbias[col],
                          d[mt][nt][1] + sbias[col + 1] };
            float2 v1 = { d[mt][nt][2] + sbias[col],
                          d[mt][nt][3] + sbias[col + 1] };
            *(float2*)cp0 = v0;
            *(float2*)cp1 = v1;
        }
    }
}

// ---------------- persistent LSTM scan — tensor-core recurrence -------------------
// 128 CTAs x 256 threads (8 warps). CTA owns hidden cols bid*4..+3 for all 4
// gates -> B tile = 16 w_hh rows (n = gate*4+j), converted to bf16 hi/lo ONCE and
// kept as register-resident mma fragments. Per step: h (16x512 fp32) staged +
// split to bf16 hi/lo smem image (80B rows, ldmatrix-friendly), warp w does
// k-slice 64: 8 ldsm4 + 24 HMMA (3-term split). Cross-warp reduce + fp32 act.
#define CONV_HALF 20480                       // 16 kb x 16 rows x 80 B
#define SCAN_DYN  (2 * CONV_HALF)

__global__ __launch_bounds__(256, 1)
void lstm_scan_kernel(const float* __restrict__ w_hh,
                      const float* __restrict__ h0,
                      const float* __restrict__ c0,
                      float* __restrict__ hout,
                      int write_y)
{
    extern __shared__ __align__(16) char conv[];
    __nv_bfloat16* sh_hi = (__nv_bfloat16*)conv;
    __nv_bfloat16* sh_lo = (__nv_bfloat16*)(conv + CONV_HALF);
    __shared__ float sh_part[8 * 264];
    __shared__ float sh_act[256];
    __shared__ float sh_c[64];

    const int tid  = threadIdx.x;
    const int bid  = blockIdx.x;
    const int lane = tid & 31;
    const int wrp  = tid >> 5;

    const u32 hi_base = cvta_s(sh_hi);
    const u32 lo_base = cvta_s(sh_lo);

    // split-convert a float2 into the [kblock][row][40] bf16 image (k even)
    auto cvt_store = [&](float2 v, int row, int k) {
        __nv_bfloat16 h0b = __float2bfloat16(v.x);
        __nv_bfloat16 h1b = __float2bfloat16(v.y);
        __nv_bfloat16 l0b = __float2bfloat16(v.x - __bfloat162float(h0b));
        __nv_bfloat16 l1b = __float2bfloat16(v.y - __bfloat162float(h1b));
        int off = ((k >> 5) * 16 + row) * 40 + (k & 31);
        __nv_bfloat162 hp; hp.x = h0b; hp.y = h1b;
        __nv_bfloat162 lp; lp.x = l0b; lp.y = l1b;
        *(__nv_bfloat162*)&sh_hi[off] = hp;
        *(__nv_bfloat162*)&sh_lo[off] = lp;
    };

    // ---- init: h0/c0, then build register-resident B fragments from w_hh ----
    if (tid < 64) {
        g_h[0][bid * 64 + tid] = h0[bid * 64 + tid];
        sh_c[tid] = c0[(tid >> 2) * HH + bid * 4 + (tid & 3)];
    }
#pragma unroll
    for (int p = 0; p < 16; p++) {
        int i2 = tid + 256 * p;
        int n = i2 >> 8, k = (i2 & 255) * 2;
        int grow = (n >> 2) * HH + bid * 4 + (n & 3);
        float2 v = *(const float2*)&w_hh[(size_t)grow * HH + k];
        cvt_store(v, n, k);
    }
    __syncthreads();

    u32 bh[4][2][2], bl[4][2][2];
#pragma unroll
    for (int ts = 0; ts < 4; ts++)
#pragma unroll
        for (int nt = 0; nt < 2; nt++) {
            u32 off = (u32)(((wrp * 2 + (ts >> 1)) * 16 + nt * 8 + (lane & 7)) * 80
                            + (ts & 1) * 32 + ((lane >> 3) & 1) * 16);
            ldsm2(bh[ts][nt], hi_base + off);
            ldsm2(bl[ts][nt], lo_base + off);
        }
    __syncthreads();   // B image fully consumed before h reuses the buffer

    // act-phase identity: batch ab, gate ag, column aj
    const int ab = tid >> 4;
    const int ag = (tid & 15) >> 2;
    const int aj = tid & 3;
    const size_t gx_base = (size_t)ab * TT * G4 + ag * HH + bid * 4 + aj;

    grid_barrier(NB);
    float gxv = __ldg(&g_gx[gx_base]);

#pragma unroll 1
    for (int t = 0; t < TT; t++) {
        // stage h (L2 broadcast) + split-convert to bf16 hi/lo image
        const float* cur = g_h[t & 1];
#pragma unroll
        for (int p = 0; p < 16; p++) {
            int i2 = tid + 256 * p;
            int b = i2 >> 8, k = (i2 & 255) * 2;
            float2 v = __ldcg((const float2*)&cur[b * HH + k]);
            cvt_store(v, b, k);
        }
        __syncthreads();

        float gxn = (t + 1 < TT) ? __ldg(&g_gx[gx_base + (size_t)(t + 1) * G4]) : 0.f;

        // A fragments: warp wrp covers k in [wrp*64, wrp*64+64)
        u32 ah[4][4], al[4][4];
#pragma unroll
        for (int ts = 0; ts < 4; ts++) {
            u32 off = (u32)(((wrp * 2 + (ts >> 1)) * 16 + (lane & 15)) * 80
                            + (ts & 1) * 32 + (lane >> 4) * 16);
            ldsm4(ah[ts], hi_base + off);
            ldsm4(al[ts], lo_base + off);
        }

        float d[2][4];
#pragma unroll
        for (int nt = 0; nt < 2; nt++)
#pragma unroll
            for (int q = 0; q < 4; q++) d[nt][q] = 0.f;

#pragma unroll
        for (int ts = 0; ts < 4; ts++)
#pragma unroll
            for (int nt = 0; nt < 2; nt++) {
                mma16816(d[nt], ah[ts], bh[ts][nt]);
                mma16816(d[nt], ah[ts], bl[ts][nt]);
                mma16816(d[nt], al[ts], bh[ts][nt]);
            }

        // partial store: D frag (m16n16) -> sh_part[wrp][m*16+n]
#pragma unroll
        for (int nt = 0; nt < 2; nt++)
#pragma unroll
            for (int q = 0; q < 4; q++) {
                int m = (lane >> 2) + (q >> 1) * 8;
                int n = nt * 8 + 2 * (lane & 3) + (q & 1);
                sh_part[wrp * 264 + m * 16 + n] = d[nt][q];
            }
        __syncthreads();

        // reduce 8 warps + gx, activate (one gate value per thread)
        float s = gxv;
#pragma unroll
        for (int p = 0; p < 8; p++) s += sh_part[p * 264 + tid];
        float v = (ag == 2) ? tanhf(s) : 1.0f / (1.0f + expf(-s));
        sh_act[tid] = v;
        __syncthreads();

        if (tid < 64) {
            int b = tid >> 2, jj = tid & 3;
            float iv = sh_act[b * 16 + 0  + jj];
            float fv = sh_act[b * 16 + 4  + jj];
            float gv = sh_act[b * 16 + 8  + jj];
            float ov = sh_act[b * 16 + 12 + jj];
            float c = fv * sh_c[tid] + iv * gv;
            sh_c[tid] = c;
            float h = ov * tanhf(c);
            int col = bid * 4 + jj;
            g_h[(t + 1) & 1][b * HH + col] = h;
            if (write_y) g_y[((size_t)b * TT + t) * HH + col] = h;
            if (t == TT - 1) hout[b * HH + col] = h;
        }
        gxv = gxn;
        grid_barrier(NB);
    }
}

// ---------------- launch -----------------------------------------------------------
extern "C" void kernel_launch(void* const* d_in, const int* in_sizes, int n_in,
                              void* d_out, int out_size)
{
    const float* x     = (const float*)d_in[0];
    const float* h0    = (const float*)d_in[1];
    const float* c0    = (const float*)d_in[2];
    const float* w_ih0 = (const float*)d_in[3];
    const float* w_hh0 = (const float*)d_in[4];
    const float* b_ih0 = (const float*)d_in[5];
    const float* b_hh0 = (const float*)d_in[6];
    const float* w_ih1 = (const float*)d_in[7];
    const float* w_hh1 = (const float*)d_in[8];
    const float* b_ih1 = (const float*)d_in[9];
    const float* b_hh1 = (const float*)d_in[10];
    float* out = (float*)d_out;

    cudaFuncSetAttribute(gemm_hmma, cudaFuncAttributeMaxDynamicSharedMemorySize,
                         SMEM_DYN);
    // FIX: scan kernel's dynamic smem (40KB) + static (~9.7KB) exceeds the
    // default 48KB combined limit -> must opt in explicitly.
    cudaFuncSetAttribute(lstm_scan_kernel, cudaFuncAttributeMaxDynamicSharedMemorySize,
                         SCAN_DYN);

    __nv_bfloat16 *ahi, *alo, *w0hi, *w0lo, *w1hi, *w1lo;
    cudaGetSymbolAddress((void**)&ahi,  g_ahi);
    cudaGetSymbolAddress((void**)&alo,  g_alo);
    cudaGetSymbolAddress((void**)&w0hi, g_whi); w1hi = w0hi + G4 * KK;
    cudaGetSymbolAddress((void**)&w0lo, g_wlo); w1lo = w0lo + G4 * KK;

    const int NW4 = (G4 * KK) / 4;
    const int NA4 = (BB * TT * HH) / 4;
    dim3 ggrid(G4 / 128, (BB * TT) / 128);

    conv_split<<<(NW4 + 255) / 256, 256>>>(w_ih0, 0, w0hi, w0lo, NW4);
    conv_split<<<(NW4 + 255) / 256, 256>>>(w_ih1, 0, w1hi, w1lo, NW4);

    // layer 0
    conv_split<<<(NA4 + 255) / 256, 256>>>(x, 0, ahi, alo, NA4);
    gemm_hmma<<<ggrid, 256, SMEM_DYN>>>(ahi, alo, w0hi, w0lo, b_ih0, b_hh0);
    lstm_scan_kernel<<<NB, 256, SCAN_DYN>>>(w_hh0, h0, c0, out, 1);

    // layer 1
    conv_split<<<(NA4 + 255) / 256, 256>>>(nullptr, 1, ahi, alo, NA4);
    gemm_hmma<<<ggrid, 256, SMEM_DYN>>>(ahi, alo, w1hi, w1lo, b_ih1, b_hh1);
    lstm_scan_kernel<<<NB, 256, SCAN_DYN>>>(w_hh1, h0 + BB * HH, c0 + BB * HH,
                                            out + BB * HH, 0);
}